// round 1
// baseline (speedup 1.0000x reference)
#include <cuda_runtime.h>
#include <cuda_bf16.h>
#include <math.h>

// ---------------------------------------------------------------------------
// blockLayer: out[b, 3n+k] = sum_d input[b,d] * B[n,d,k],  B = M^T M (3x3 sym)
// M = [[sp(w0), w1, w2], [0, sp(w3), w4], [0, 0, sp(w5)]]
// Write-bound: output is 402.6 MB fp32. Strategy: precompute B (6 sym values,
// padded to 8 floats/n), then stream output with coalesced float4 stores,
// amortizing B register loads over a 16-batch tile.
// ---------------------------------------------------------------------------

#define MAX_N 8192
#define BT 16            // batch rows per block
#define NPT 4            // n's per thread
#define TPB 256          // threads per block
#define N_PER_BLOCK (TPB * NPT)   // 1024

// Scratch: 8 floats per n (b00,b01,b02,b11 | b12,b22,pad,pad) = 256 KB
__device__ float4 g_B[MAX_N * 2];

__device__ __forceinline__ float softplus_f(float x) {
    // matches jax.nn.softplus = log1p(exp(x)); stable for large x
    return (x > 20.0f) ? x : log1pf(expf(x));
}

__global__ void build_B_kernel(const float* __restrict__ w, int n) {
    int i = blockIdx.x * blockDim.x + threadIdx.x;
    if (i >= n) return;
    float a = softplus_f(w[i * 6 + 0]);
    float b = w[i * 6 + 1];
    float c = w[i * 6 + 2];
    float d = softplus_f(w[i * 6 + 3]);
    float e = w[i * 6 + 4];
    float f = softplus_f(w[i * 6 + 5]);
    // B = M^T M (symmetric)
    float B00 = a * a;
    float B01 = a * b;
    float B02 = a * c;
    float B11 = b * b + d * d;
    float B12 = b * c + d * e;
    float B22 = c * c + e * e + f * f;
    g_B[i * 2 + 0] = make_float4(B00, B01, B02, B11);
    g_B[i * 2 + 1] = make_float4(B12, B22, 0.0f, 0.0f);
}

__global__ __launch_bounds__(TPB)
void apply_kernel(const float* __restrict__ x, float* __restrict__ out,
                  int batch, int n) {
    __shared__ float sx[BT * 3];

    const int n0 = blockIdx.x * N_PER_BLOCK + threadIdx.x * NPT;  // first n for this thread
    const int b0 = blockIdx.y * BT;

    // Load B for my 4 n's into registers (8 float4 loads; L2-resident)
    float4 Ba[NPT], Bb[NPT];
    bool valid = (n0 + NPT <= n);
    if (valid) {
        #pragma unroll
        for (int j = 0; j < NPT; j++) {
            Ba[j] = g_B[(n0 + j) * 2 + 0];
            Bb[j] = g_B[(n0 + j) * 2 + 1];
        }
    }

    // Stage x tile into smem (BT*3 = 48 floats)
    if (threadIdx.x < BT * 3) {
        int idx = b0 * 3 + threadIdx.x;
        sx[threadIdx.x] = (idx < batch * 3) ? x[idx] : 0.0f;
    }
    __syncthreads();

    if (!valid) return;

    const size_t row_stride = (size_t)n * 3;

    #pragma unroll 1
    for (int bb = 0; bb < BT; bb++) {
        int b = b0 + bb;
        if (b >= batch) break;
        float x0 = sx[bb * 3 + 0];
        float x1 = sx[bb * 3 + 1];
        float x2 = sx[bb * 3 + 2];

        float o[NPT * 3];
        #pragma unroll
        for (int j = 0; j < NPT; j++) {
            // out_k = x0*B[0][k] + x1*B[1][k] + x2*B[2][k], symmetric B
            o[j * 3 + 0] = fmaf(x0, Ba[j].x, fmaf(x1, Ba[j].y, x2 * Ba[j].z));
            o[j * 3 + 1] = fmaf(x0, Ba[j].y, fmaf(x1, Ba[j].w, x2 * Bb[j].x));
            o[j * 3 + 2] = fmaf(x0, Ba[j].z, fmaf(x1, Bb[j].x, x2 * Bb[j].y));
        }

        // 12 contiguous floats at out[b, n0*3] -> 3 aligned float4 streaming stores
        float* dst = out + (size_t)b * row_stride + (size_t)n0 * 3;
        float4 v0 = make_float4(o[0], o[1], o[2], o[3]);
        float4 v1 = make_float4(o[4], o[5], o[6], o[7]);
        float4 v2 = make_float4(o[8], o[9], o[10], o[11]);
        __stcs(reinterpret_cast<float4*>(dst) + 0, v0);
        __stcs(reinterpret_cast<float4*>(dst) + 1, v1);
        __stcs(reinterpret_cast<float4*>(dst) + 2, v2);
    }
}

extern "C" void kernel_launch(void* const* d_in, const int* in_sizes, int n_in,
                              void* d_out, int out_size) {
    const float* inp = (const float*)d_in[0];   // (batch, 3)
    const float* w   = (const float*)d_in[1];   // (n, 6)
    float* out = (float*)d_out;

    int batch = in_sizes[0] / 3;
    int n     = in_sizes[1] / 6;

    // Kernel 1: build B (tiny)
    int blocks1 = (n + TPB - 1) / TPB;
    build_B_kernel<<<blocks1, TPB>>>(w, n);

    // Kernel 2: stream output
    dim3 grid((n + N_PER_BLOCK - 1) / N_PER_BLOCK, (batch + BT - 1) / BT);
    apply_kernel<<<grid, TPB>>>(inp, out, batch, n);
}

// round 2
// speedup vs baseline: 2.2921x; 2.2921x over previous
#include <cuda_runtime.h>
#include <cuda_bf16.h>
#include <math.h>

// ---------------------------------------------------------------------------
// blockLayer: out[b, 3n+k] = x[b,:] . B[n][:,k],  B = M^T M (3x3 symmetric)
// Pure HBM-write-bound (402.6 MB out). Round 2: lane-contiguous float4 output
// mapping for perfect store coalescing. Each thread owns QPT float4 columns of
// the output row; the 12 dot coefficients per float4 are batch-invariant and
// hoisted to registers; inner loop over a 16-batch tile = 12 FMA + 1 STG.128.
// ---------------------------------------------------------------------------

#define MAX_N 8192
#define BT 16            // batch rows per block
#define QPT 4            // float4 output columns per thread
#define TPB 256          // threads per block

// Scratch: per n: (B00,B01,B02,B11) | (B12,B22,pad,pad) = 256 KB, L2-resident
__device__ float4 g_B[MAX_N * 2];

__device__ __forceinline__ float softplus_f(float x) {
    return (x > 20.0f) ? x : log1pf(expf(x));
}

__global__ void build_B_kernel(const float* __restrict__ w, int n) {
    int i = blockIdx.x * blockDim.x + threadIdx.x;
    if (i >= n) return;
    float a = softplus_f(w[i * 6 + 0]);
    float b = w[i * 6 + 1];
    float c = w[i * 6 + 2];
    float d = softplus_f(w[i * 6 + 3]);
    float e = w[i * 6 + 4];
    float f = softplus_f(w[i * 6 + 5]);
    float B00 = a * a;
    float B01 = a * b;
    float B02 = a * c;
    float B11 = b * b + d * d;
    float B12 = b * c + d * e;
    float B22 = c * c + e * e + f * f;
    g_B[i * 2 + 0] = make_float4(B00, B01, B02, B11);
    g_B[i * 2 + 1] = make_float4(B12, B22, 0.0f, 0.0f);
}

// Extract column k of symmetric B given packed (lo, hi).
__device__ __forceinline__ void b_col(const float4& lo, const float4& hi, int k,
                                      float& c0, float& c1, float& c2) {
    if (k == 0)      { c0 = lo.x; c1 = lo.y; c2 = lo.z; }
    else if (k == 1) { c0 = lo.y; c1 = lo.w; c2 = hi.x; }
    else             { c0 = lo.z; c1 = hi.x; c2 = hi.y; }
}

__global__ __launch_bounds__(TPB)
void apply_kernel(const float* __restrict__ x, float4* __restrict__ out,
                  int batch, int n) {
    __shared__ float sx[BT * 3];

    const int q_row = (3 * n) / 4;           // float4 columns per output row
    const int b0 = blockIdx.y * BT;

    // Stage x tile into smem
    if (threadIdx.x < BT * 3) {
        int idx = b0 * 3 + threadIdx.x;
        sx[threadIdx.x] = (idx < batch * 3) ? x[idx] : 0.0f;
    }
    __syncthreads();

    // Per-thread batch-invariant coefficients: c[i][j][0..2] for output float
    // j of float4 column q_i.  q = qbase + i*TPB + tid  (lane-contiguous!)
    float c0[QPT][4], c1[QPT][4], c2[QPT][4];
    int   q_of[QPT];
    bool  qv[QPT];

    const int qbase = blockIdx.x * (TPB * QPT) + threadIdx.x;
    #pragma unroll
    for (int i = 0; i < QPT; i++) {
        int q = qbase + i * TPB;
        q_of[i] = q;
        qv[i] = (q < q_row);
        if (qv[i]) {
            int f0 = 4 * q;
            int n0 = f0 / 3;
            int k0 = f0 % 3;
            int n1 = (n0 + 1 < n) ? (n0 + 1) : n0;   // guard (never hit for aligned shapes)
            float4 Alo = g_B[n0 * 2 + 0];
            float4 Ahi = g_B[n0 * 2 + 1];
            float4 Clo = g_B[n1 * 2 + 0];
            float4 Chi = g_B[n1 * 2 + 1];
            #pragma unroll
            for (int j = 0; j < 4; j++) {
                int kk = k0 + j;
                if (kk < 3) b_col(Alo, Ahi, kk,     c0[i][j], c1[i][j], c2[i][j]);
                else        b_col(Clo, Chi, kk - 3, c0[i][j], c1[i][j], c2[i][j]);
            }
        }
    }

    // Batch loop: 12 FMA + 1 coalesced STG.128 per (i, b)
    #pragma unroll 2
    for (int bb = 0; bb < BT; bb++) {
        int b = b0 + bb;
        if (b >= batch) break;
        float x0 = sx[bb * 3 + 0];
        float x1 = sx[bb * 3 + 1];
        float x2 = sx[bb * 3 + 2];
        float4* row = out + (size_t)b * q_row;
        #pragma unroll
        for (int i = 0; i < QPT; i++) {
            if (!qv[i]) continue;
            float4 v;
            v.x = fmaf(x0, c0[i][0], fmaf(x1, c1[i][0], x2 * c2[i][0]));
            v.y = fmaf(x0, c0[i][1], fmaf(x1, c1[i][1], x2 * c2[i][1]));
            v.z = fmaf(x0, c0[i][2], fmaf(x1, c1[i][2], x2 * c2[i][2]));
            v.w = fmaf(x0, c0[i][3], fmaf(x1, c1[i][3], x2 * c2[i][3]));
            __stcs(row + q_of[i], v);
        }
    }
}

extern "C" void kernel_launch(void* const* d_in, const int* in_sizes, int n_in,
                              void* d_out, int out_size) {
    const float* inp = (const float*)d_in[0];   // (batch, 3)
    const float* w   = (const float*)d_in[1];   // (n, 6)
    float4* out = (float4*)d_out;

    int batch = in_sizes[0] / 3;
    int n     = in_sizes[1] / 6;
    int q_row = (3 * n) / 4;

    build_B_kernel<<<(n + TPB - 1) / TPB, TPB>>>(w, n);

    dim3 grid((q_row + TPB * QPT - 1) / (TPB * QPT), (batch + BT - 1) / BT);
    apply_kernel<<<grid, TPB>>>(inp, out, batch, n);
}

// round 3
// speedup vs baseline: 2.3949x; 1.0449x over previous
#include <cuda_runtime.h>
#include <cuda_bf16.h>
#include <math.h>

// ---------------------------------------------------------------------------
// blockLayer: out[b, 3n+k] = x[b,:] . B[n][:,k],  B = M^T M (3x3 symmetric)
// Pure HBM-write-bound (402.6 MB out). Round 3: QPT=2 to cut register
// pressure (68 -> ~42 regs), lifting the register-occupancy cap from 3 to 6
// CTAs/SM so enough stores are in flight to saturate HBM write bandwidth.
// Store mapping unchanged: lane-contiguous float4 columns, STG.128 .cs.
// ---------------------------------------------------------------------------

#define MAX_N 8192
#define BT 16            // batch rows per block
#define QPT 2            // float4 output columns per thread
#define TPB 256          // threads per block

// Scratch: per n: (B00,B01,B02,B11) | (B12,B22,pad,pad) = 256 KB, L2-resident
__device__ float4 g_B[MAX_N * 2];

__device__ __forceinline__ float softplus_f(float x) {
    return (x > 20.0f) ? x : log1pf(expf(x));
}

__global__ void build_B_kernel(const float* __restrict__ w, int n) {
    int i = blockIdx.x * blockDim.x + threadIdx.x;
    if (i >= n) return;
    float a = softplus_f(w[i * 6 + 0]);
    float b = w[i * 6 + 1];
    float c = w[i * 6 + 2];
    float d = softplus_f(w[i * 6 + 3]);
    float e = w[i * 6 + 4];
    float f = softplus_f(w[i * 6 + 5]);
    float B00 = a * a;
    float B01 = a * b;
    float B02 = a * c;
    float B11 = b * b + d * d;
    float B12 = b * c + d * e;
    float B22 = c * c + e * e + f * f;
    g_B[i * 2 + 0] = make_float4(B00, B01, B02, B11);
    g_B[i * 2 + 1] = make_float4(B12, B22, 0.0f, 0.0f);
}

// Extract column k of symmetric B given packed (lo, hi).
__device__ __forceinline__ void b_col(const float4& lo, const float4& hi, int k,
                                      float& c0, float& c1, float& c2) {
    if (k == 0)      { c0 = lo.x; c1 = lo.y; c2 = lo.z; }
    else if (k == 1) { c0 = lo.y; c1 = lo.w; c2 = hi.x; }
    else             { c0 = lo.z; c1 = hi.x; c2 = hi.y; }
}

__global__ __launch_bounds__(TPB, 6)
void apply_kernel(const float* __restrict__ x, float4* __restrict__ out,
                  int batch, int n) {
    __shared__ float sx[BT * 3];

    const int q_row = (3 * n) / 4;           // float4 columns per output row
    const int b0 = blockIdx.y * BT;

    // Stage x tile into smem
    if (threadIdx.x < BT * 3) {
        int idx = b0 * 3 + threadIdx.x;
        sx[threadIdx.x] = (idx < batch * 3) ? x[idx] : 0.0f;
    }
    __syncthreads();

    // Per-thread batch-invariant coefficients for QPT lane-contiguous float4
    // columns: q_i = blockIdx.x*TPB*QPT + i*TPB + tid
    float c0[QPT][4], c1[QPT][4], c2[QPT][4];
    int   q_of[QPT];
    bool  qv[QPT];

    const int qbase = blockIdx.x * (TPB * QPT) + threadIdx.x;
    #pragma unroll
    for (int i = 0; i < QPT; i++) {
        int q = qbase + i * TPB;
        q_of[i] = q;
        qv[i] = (q < q_row);
        if (qv[i]) {
            int f0 = 4 * q;
            int n0 = f0 / 3;
            int k0 = f0 % 3;
            int n1 = (n0 + 1 < n) ? (n0 + 1) : n0;
            float4 Alo = g_B[n0 * 2 + 0];
            float4 Ahi = g_B[n0 * 2 + 1];
            float4 Clo = g_B[n1 * 2 + 0];
            float4 Chi = g_B[n1 * 2 + 1];
            #pragma unroll
            for (int j = 0; j < 4; j++) {
                int kk = k0 + j;
                if (kk < 3) b_col(Alo, Ahi, kk,     c0[i][j], c1[i][j], c2[i][j]);
                else        b_col(Clo, Chi, kk - 3, c0[i][j], c1[i][j], c2[i][j]);
            }
        }
    }

    // Batch loop: 12 FMA + 1 coalesced STG.128 per (i, b)
    #pragma unroll 2
    for (int bb = 0; bb < BT; bb++) {
        int b = b0 + bb;
        if (b >= batch) break;
        float x0 = sx[bb * 3 + 0];
        float x1 = sx[bb * 3 + 1];
        float x2 = sx[bb * 3 + 2];
        float4* row = out + (size_t)b * q_row;
        #pragma unroll
        for (int i = 0; i < QPT; i++) {
            if (!qv[i]) continue;
            float4 v;
            v.x = fmaf(x0, c0[i][0], fmaf(x1, c1[i][0], x2 * c2[i][0]));
            v.y = fmaf(x0, c0[i][1], fmaf(x1, c1[i][1], x2 * c2[i][1]));
            v.z = fmaf(x0, c0[i][2], fmaf(x1, c1[i][2], x2 * c2[i][2]));
            v.w = fmaf(x0, c0[i][3], fmaf(x1, c1[i][3], x2 * c2[i][3]));
            __stcs(row + q_of[i], v);
        }
    }
}

extern "C" void kernel_launch(void* const* d_in, const int* in_sizes, int n_in,
                              void* d_out, int out_size) {
    const float* inp = (const float*)d_in[0];   // (batch, 3)
    const float* w   = (const float*)d_in[1];   // (n, 6)
    float4* out = (float4*)d_out;

    int batch = in_sizes[0] / 3;
    int n     = in_sizes[1] / 6;
    int q_row = (3 * n) / 4;

    build_B_kernel<<<(n + TPB - 1) / TPB, TPB>>>(w, n);

    dim3 grid((q_row + TPB * QPT - 1) / (TPB * QPT), (batch + BT - 1) / BT);
    apply_kernel<<<grid, TPB>>>(inp, out, batch, n);
}

// round 4
// speedup vs baseline: 2.4329x; 1.0158x over previous
#include <cuda_runtime.h>
#include <cuda_bf16.h>
#include <math.h>

// ---------------------------------------------------------------------------
// blockLayer: out[b, 3n+k] = x[b,:] . B[n][:,k],  B = M^T M (3x3 symmetric)
// Pure HBM-write-bound (402.6 MB fp32 out). Round 4: QPT=1 / BT=32 /
// launch_bounds(256,8) -> ~30 regs, 8 CTAs/SM, 100% occupancy; x4-unrolled
// batch loop keeps 4 independent coalesced STG.128 per warp in flight.
// ---------------------------------------------------------------------------

#define MAX_N 8192
#define BT 32            // batch rows per block
#define TPB 256          // threads per block; each thread owns ONE float4 col

// Scratch: per n: (B00,B01,B02,B11) | (B12,B22,pad,pad) = 256 KB, L2-resident
__device__ float4 g_B[MAX_N * 2];

__device__ __forceinline__ float softplus_f(float x) {
    return (x > 20.0f) ? x : log1pf(expf(x));
}

__global__ void build_B_kernel(const float* __restrict__ w, int n) {
    int i = blockIdx.x * blockDim.x + threadIdx.x;
    if (i >= n) return;
    float a = softplus_f(w[i * 6 + 0]);
    float b = w[i * 6 + 1];
    float c = w[i * 6 + 2];
    float d = softplus_f(w[i * 6 + 3]);
    float e = w[i * 6 + 4];
    float f = softplus_f(w[i * 6 + 5]);
    float B00 = a * a;
    float B01 = a * b;
    float B02 = a * c;
    float B11 = b * b + d * d;
    float B12 = b * c + d * e;
    float B22 = c * c + e * e + f * f;
    g_B[i * 2 + 0] = make_float4(B00, B01, B02, B11);
    g_B[i * 2 + 1] = make_float4(B12, B22, 0.0f, 0.0f);
}

// Extract column k of symmetric B given packed (lo, hi).
__device__ __forceinline__ void b_col(const float4& lo, const float4& hi, int k,
                                      float& c0, float& c1, float& c2) {
    if (k == 0)      { c0 = lo.x; c1 = lo.y; c2 = lo.z; }
    else if (k == 1) { c0 = lo.y; c1 = lo.w; c2 = hi.x; }
    else             { c0 = lo.z; c1 = hi.x; c2 = hi.y; }
}

__global__ __launch_bounds__(TPB, 8)
void apply_kernel(const float* __restrict__ x, float4* __restrict__ out,
                  int batch, int n) {
    __shared__ float sx[BT * 3];

    const int q_row = (3 * n) / 4;           // float4 columns per output row
    const int b0 = blockIdx.y * BT;

    // Stage x tile into smem (BT*3 = 96 floats)
    if (threadIdx.x < BT * 3) {
        int idx = b0 * 3 + threadIdx.x;
        sx[threadIdx.x] = (idx < batch * 3) ? x[idx] : 0.0f;
    }
    __syncthreads();

    // This thread's single float4 output column (lane-contiguous -> coalesced)
    const int q = blockIdx.x * TPB + threadIdx.x;
    if (q >= q_row) return;

    // Batch-invariant coefficients: out4[j] = x0*c0[j] + x1*c1[j] + x2*c2[j]
    float c0[4], c1[4], c2[4];
    {
        int f0 = 4 * q;
        int n0 = f0 / 3;
        int k0 = f0 % 3;
        int n1 = (n0 + 1 < n) ? (n0 + 1) : n0;
        float4 Alo = g_B[n0 * 2 + 0];
        float4 Ahi = g_B[n0 * 2 + 1];
        float4 Clo = g_B[n1 * 2 + 0];
        float4 Chi = g_B[n1 * 2 + 1];
        #pragma unroll
        for (int j = 0; j < 4; j++) {
            int kk = k0 + j;
            if (kk < 3) b_col(Alo, Ahi, kk,     c0[j], c1[j], c2[j]);
            else        b_col(Clo, Chi, kk - 3, c0[j], c1[j], c2[j]);
        }
    }

    float4* dst = out + (size_t)b0 * q_row + q;
    const size_t stride = q_row;
    const int bmax = (batch - b0 < BT) ? (batch - b0) : BT;

    #pragma unroll 4
    for (int bb = 0; bb < bmax; bb++) {
        float x0 = sx[bb * 3 + 0];
        float x1 = sx[bb * 3 + 1];
        float x2 = sx[bb * 3 + 2];
        float4 v;
        v.x = fmaf(x0, c0[0], fmaf(x1, c1[0], x2 * c2[0]));
        v.y = fmaf(x0, c0[1], fmaf(x1, c1[1], x2 * c2[1]));
        v.z = fmaf(x0, c0[2], fmaf(x1, c1[2], x2 * c2[2]));
        v.w = fmaf(x0, c0[3], fmaf(x1, c1[3], x2 * c2[3]));
        __stcs(dst, v);
        dst += stride;
    }
}

extern "C" void kernel_launch(void* const* d_in, const int* in_sizes, int n_in,
                              void* d_out, int out_size) {
    const float* inp = (const float*)d_in[0];   // (batch, 3)
    const float* w   = (const float*)d_in[1];   // (n, 6)
    float4* out = (float4*)d_out;

    int batch = in_sizes[0] / 3;
    int n     = in_sizes[1] / 6;
    int q_row = (3 * n) / 4;

    build_B_kernel<<<(n + TPB - 1) / TPB, TPB>>>(w, n);

    dim3 grid((q_row + TPB - 1) / TPB, (batch + BT - 1) / BT);
    apply_kernel<<<grid, TPB>>>(inp, out, batch, n);
}

// round 5
// speedup vs baseline: 2.4721x; 1.0161x over previous
#include <cuda_runtime.h>
#include <cuda_bf16.h>
#include <math.h>

// ---------------------------------------------------------------------------
// blockLayer: out[b, 3n+k] = x[b,:] . B[n][:,k],  B = M^T M (3x3 symmetric)
// Pure HBM-write-bound (402.6 MB fp32 out). Round 5: FUSED single kernel —
// each thread derives its two needed B matrices directly from w (L2-resident,
// 192 KB), eliminating the separate build kernel (+~5us) and its launch gap.
// BT=42 tunes the grid to 1.99 full waves (2352 blocks vs 1184 slots).
// Store mapping: lane-contiguous float4 output columns, STG.128 .cs.
// ---------------------------------------------------------------------------

#define BT 42            // batch rows per block  -> 98 tiles -> 2352 blocks
#define TPB 256          // threads per block; each thread owns ONE float4 col

__device__ __forceinline__ float softplus_f(float x) {
    return (x > 20.0f) ? x : log1pf(expf(x));
}

// Compute packed symmetric B = M^T M for weight row wr (6 floats, 8B aligned).
__device__ __forceinline__ void make_B(const float* __restrict__ wr,
                                       float4& lo, float4& hi) {
    float2 p0 = *reinterpret_cast<const float2*>(wr + 0);
    float2 p1 = *reinterpret_cast<const float2*>(wr + 2);
    float2 p2 = *reinterpret_cast<const float2*>(wr + 4);
    float a = softplus_f(p0.x);
    float b = p0.y;
    float c = p1.x;
    float d = softplus_f(p1.y);
    float e = p2.x;
    float f = softplus_f(p2.y);
    lo.x = a * a;                       // B00
    lo.y = a * b;                       // B01
    lo.z = a * c;                       // B02
    lo.w = b * b + d * d;               // B11
    hi.x = b * c + d * e;               // B12
    hi.y = c * c + e * e + f * f;       // B22
    hi.z = 0.0f; hi.w = 0.0f;
}

// Extract column k of symmetric B given packed (lo, hi).
__device__ __forceinline__ void b_col(const float4& lo, const float4& hi, int k,
                                      float& c0, float& c1, float& c2) {
    if (k == 0)      { c0 = lo.x; c1 = lo.y; c2 = lo.z; }
    else if (k == 1) { c0 = lo.y; c1 = lo.w; c2 = hi.x; }
    else             { c0 = lo.z; c1 = hi.x; c2 = hi.y; }
}

__global__ __launch_bounds__(TPB, 8)
void fused_kernel(const float* __restrict__ x, const float* __restrict__ w,
                  float4* __restrict__ out, int batch, int n) {
    __shared__ float sx[BT * 3];

    const int q_row = (3 * n) / 4;           // float4 columns per output row
    const int b0 = blockIdx.y * BT;

    // Stage x tile into smem (BT*3 = 126 floats)
    if (threadIdx.x < BT * 3) {
        int idx = b0 * 3 + threadIdx.x;
        sx[threadIdx.x] = (idx < batch * 3) ? x[idx] : 0.0f;
    }
    __syncthreads();

    // This thread's single float4 output column (lane-contiguous -> coalesced)
    const int q = blockIdx.x * TPB + threadIdx.x;
    if (q >= q_row) return;

    // Derive the (at most) two B matrices this float4 touches, then the
    // batch-invariant coefficients: out4[j] = x0*c0[j] + x1*c1[j] + x2*c2[j]
    float c0[4], c1[4], c2[4];
    {
        int f0 = 4 * q;
        int n0 = f0 / 3;
        int k0 = f0 - 3 * n0;
        int n1 = (n0 + 1 < n) ? (n0 + 1) : (n - 1);
        float4 Alo, Ahi, Clo, Chi;
        make_B(w + (size_t)n0 * 6, Alo, Ahi);
        make_B(w + (size_t)n1 * 6, Clo, Chi);
        #pragma unroll
        for (int j = 0; j < 4; j++) {
            int kk = k0 + j;
            if (kk < 3) b_col(Alo, Ahi, kk,     c0[j], c1[j], c2[j]);
            else        b_col(Clo, Chi, kk - 3, c0[j], c1[j], c2[j]);
        }
    }

    float4* dst = out + (size_t)b0 * q_row + q;
    const size_t stride = q_row;
    const int bmax = (batch - b0 < BT) ? (batch - b0) : BT;

    #pragma unroll 4
    for (int bb = 0; bb < bmax; bb++) {
        float x0 = sx[bb * 3 + 0];
        float x1 = sx[bb * 3 + 1];
        float x2 = sx[bb * 3 + 2];
        float4 v;
        v.x = fmaf(x0, c0[0], fmaf(x1, c1[0], x2 * c2[0]));
        v.y = fmaf(x0, c0[1], fmaf(x1, c1[1], x2 * c2[1]));
        v.z = fmaf(x0, c0[2], fmaf(x1, c1[2], x2 * c2[2]));
        v.w = fmaf(x0, c0[3], fmaf(x1, c1[3], x2 * c2[3]));
        __stcs(dst, v);
        dst += stride;
    }
}

extern "C" void kernel_launch(void* const* d_in, const int* in_sizes, int n_in,
                              void* d_out, int out_size) {
    const float* inp = (const float*)d_in[0];   // (batch, 3)
    const float* w   = (const float*)d_in[1];   // (n, 6)
    float4* out = (float4*)d_out;

    int batch = in_sizes[0] / 3;
    int n     = in_sizes[1] / 6;
    int q_row = (3 * n) / 4;

    dim3 grid((q_row + TPB - 1) / TPB, (batch + BT - 1) / BT);
    fused_kernel<<<grid, TPB>>>(inp, w, out, batch, n);
}